// round 14
// baseline (speedup 1.0000x reference)
#include <cuda_runtime.h>
#include <cuda_fp16.h>
#include <cuda_bf16.h>
#include <stdint.h>

// ---------------------------------------------------------------------------
// GraphConv: out = SpMM(adj, x@W + lin_bias) + bias
// GEMM(+fused hist): mma m16n8k16 bf16 3-term hi/lo, W staged once,
//   double-buffered x staging. Hist blocks ride along in the same launch.
// Scan: single-pass decoupled lookback. Then scatter, then warp-per-row csr.
// ---------------------------------------------------------------------------

#define D 128
#define TK 32
#define XS32 20
#define WS32 132
#define NMAX 100000
#define EMAX 1600000
#define HB 256                  // hist blocks fused into gemm launch

__device__ __half g_support[NMAX * D];
__device__ int    g_rowptr[NMAX + 1];
__device__ int    g_cursor[NMAX];
__device__ unsigned long long g_scanstate[128];   // (flag<<32)|value, zeroed per call
__device__ uint2  g_edges[EMAX];

// ---------------------------------------------------------------------------
__device__ __forceinline__ void split2_bf16(float a, float b, unsigned& hi, unsigned& lo)
{
    __nv_bfloat16 ah = __float2bfloat16_rn(a);
    __nv_bfloat16 bh = __float2bfloat16_rn(b);
    __nv_bfloat16 al = __float2bfloat16_rn(a - __bfloat162float(ah));
    __nv_bfloat16 bl = __float2bfloat16_rn(b - __bfloat162float(bh));
    __nv_bfloat162 H = __halves2bfloat162(ah, bh);
    __nv_bfloat162 L = __halves2bfloat162(al, bl);
    hi = *(unsigned*)&H;
    lo = *(unsigned*)&L;
}

__device__ __forceinline__ void mma_bf16(float* d, const unsigned* a, const unsigned* b)
{
    asm("mma.sync.aligned.m16n8k16.row.col.f32.bf16.bf16.f32 "
        "{%0,%1,%2,%3}, {%4,%5,%6,%7}, {%8,%9}, {%0,%1,%2,%3};"
        : "+f"(d[0]), "+f"(d[1]), "+f"(d[2]), "+f"(d[3])
        : "r"(a[0]), "r"(a[1]), "r"(a[2]), "r"(a[3]), "r"(b[0]), "r"(b[1]));
}

// ---------------------------------------------------------------------------
// Kernel 1: blocks [0,HB): edge-row histogram. blocks [HB,..): GEMM.
// GEMM: W staged once (67.6KB), x double-buffered (2x20.5KB) -> ~108.5KB smem.
// ---------------------------------------------------------------------------
__global__ void __launch_bounds__(256, 2)
gemm_hist_kernel(const float* __restrict__ x, const float* __restrict__ W,
                 const float* __restrict__ lin_bias, __half* __restrict__ sup, int M,
                 const int* __restrict__ rows, int* __restrict__ cnt, int nE)
{
    const int tid = threadIdx.x;

    if (blockIdx.x < HB) {      // ---- histogram path ----
        for (int e = blockIdx.x * 256 + tid; e < nE; e += HB * 256)
            atomicAdd(cnt + __ldg(rows + e), 1);
        return;
    }

    // ---- GEMM path ----
    extern __shared__ unsigned sh[];
    unsigned* ws_hi = sh;                        // [64][WS32]
    unsigned* ws_lo = ws_hi + 64 * WS32;
    unsigned* xs_base = ws_lo + 64 * WS32;       // 2 buffers x (hi+lo)[128][XS32]

    const int warp = tid >> 5;
    const int lane = tid & 31;
    const int g    = lane >> 2;
    const int t4   = lane & 3;

    const int rowBase = (blockIdx.x - HB) * 128;
    const int warpRow = (warp & 3) * 32;
    const int warpCol = (warp >> 2) * 64;

    // stage ALL of W once
    for (int i = tid; i < 64 * (D / 4); i += 256) {
        int k2 = i >> 5;
        int n4 = (i & 31) * 4;
        float4 va = *(const float4*)(W + (size_t)(2 * k2)     * D + n4);
        float4 vb = *(const float4*)(W + (size_t)(2 * k2 + 1) * D + n4);
        uint4 ph, pl;
        split2_bf16(va.x, vb.x, ph.x, pl.x);
        split2_bf16(va.y, vb.y, ph.y, pl.y);
        split2_bf16(va.z, vb.z, ph.z, pl.z);
        split2_bf16(va.w, vb.w, ph.w, pl.w);
        *(uint4*)(ws_hi + k2 * WS32 + n4) = ph;
        *(uint4*)(ws_lo + k2 * WS32 + n4) = pl;
    }

    float acc[2][8][4];
#pragma unroll
    for (int mt = 0; mt < 2; mt++)
#pragma unroll
        for (int nt = 0; nt < 8; nt++)
#pragma unroll
            for (int i = 0; i < 4; i++) acc[mt][nt][i] = 0.f;

    int sm[4], skq[4];
#pragma unroll
    for (int j = 0; j < 4; j++) {
        int i = tid + j * 256;
        sm[j]  = i >> 3;
        skq[j] = (i & 7) * 4;
    }

    // prefetch + stage chunk 0 into buffer 0
    float4 pre[4];
#pragma unroll
    for (int j = 0; j < 4; j++) {
        int gm = rowBase + sm[j];
        pre[j] = (gm < M) ? *(const float4*)(x + (size_t)gm * D + skq[j])
                          : make_float4(0.f, 0.f, 0.f, 0.f);
    }
    {
        unsigned* xh = xs_base;
        unsigned* xl = xs_base + 128 * XS32;
#pragma unroll
        for (int j = 0; j < 4; j++) {
            unsigned h0, l0, h1, l1;
            split2_bf16(pre[j].x, pre[j].y, h0, l0);
            split2_bf16(pre[j].z, pre[j].w, h1, l1);
            *(uint2*)(xh + sm[j] * XS32 + (skq[j] >> 1)) = make_uint2(h0, h1);
            *(uint2*)(xl + sm[j] * XS32 + (skq[j] >> 1)) = make_uint2(l0, l1);
        }
    }
    __syncthreads();    // W + buf0 ready

#pragma unroll
    for (int c = 0; c < 4; c++) {
        // prefetch next chunk (lands during the MMAs below)
        if (c < 3) {
            int k0n = (c + 1) * TK;
#pragma unroll
            for (int j = 0; j < 4; j++) {
                int gm = rowBase + sm[j];
                pre[j] = (gm < M) ? *(const float4*)(x + (size_t)gm * D + k0n + skq[j])
                                  : make_float4(0.f, 0.f, 0.f, 0.f);
            }
        }

        unsigned* xh = xs_base + (c & 1) * (2 * 128 * XS32);
        unsigned* xl = xh + 128 * XS32;
        const int kp0 = c * (TK / 2);

#pragma unroll
        for (int ks2 = 0; ks2 < TK / 2; ks2 += 8) {
            unsigned bh[8][2], bl[8][2];
#pragma unroll
            for (int nt = 0; nt < 8; nt++) {
                int col = warpCol + nt * 8 + g;
                int kr  = kp0 + ks2 + t4;
                bh[nt][0] = ws_hi[kr       * WS32 + col];
                bh[nt][1] = ws_hi[(kr + 4) * WS32 + col];
                bl[nt][0] = ws_lo[kr       * WS32 + col];
                bl[nt][1] = ws_lo[(kr + 4) * WS32 + col];
            }
#pragma unroll
            for (int mt = 0; mt < 2; mt++) {
                int r0 = warpRow + mt * 16 + g;
                unsigned ah[4], al[4];
                ah[0] = xh[r0       * XS32 + ks2 + t4];
                ah[1] = xh[(r0 + 8) * XS32 + ks2 + t4];
                ah[2] = xh[r0       * XS32 + ks2 + t4 + 4];
                ah[3] = xh[(r0 + 8) * XS32 + ks2 + t4 + 4];
                al[0] = xl[r0       * XS32 + ks2 + t4];
                al[1] = xl[(r0 + 8) * XS32 + ks2 + t4];
                al[2] = xl[r0       * XS32 + ks2 + t4 + 4];
                al[3] = xl[(r0 + 8) * XS32 + ks2 + t4 + 4];
#pragma unroll
                for (int nt = 0; nt < 8; nt++) {
                    mma_bf16(acc[mt][nt], ah, bh[nt]);
                    mma_bf16(acc[mt][nt], ah, bl[nt]);
                    mma_bf16(acc[mt][nt], al, bh[nt]);
                }
            }
        }

        // stage next chunk into the other buffer, single sync per iter
        if (c < 3) {
            unsigned* nh = xs_base + ((c + 1) & 1) * (2 * 128 * XS32);
            unsigned* nl = nh + 128 * XS32;
#pragma unroll
            for (int j = 0; j < 4; j++) {
                unsigned h0, l0, h1, l1;
                split2_bf16(pre[j].x, pre[j].y, h0, l0);
                split2_bf16(pre[j].z, pre[j].w, h1, l1);
                *(uint2*)(nh + sm[j] * XS32 + (skq[j] >> 1)) = make_uint2(h0, h1);
                *(uint2*)(nl + sm[j] * XS32 + (skq[j] >> 1)) = make_uint2(l0, l1);
            }
            __syncthreads();
        }
    }

#pragma unroll
    for (int nt = 0; nt < 8; nt++) {
        int n = warpCol + nt * 8 + t4 * 2;
        float lb0 = lin_bias[n];
        float lb1 = lin_bias[n + 1];
#pragma unroll
        for (int mt = 0; mt < 2; mt++) {
            int gm0 = rowBase + warpRow + mt * 16 + g;
            int gm1 = gm0 + 8;
            if (gm0 < M)
                *(__half2*)(sup + (size_t)gm0 * D + n) =
                    __floats2half2_rn(acc[mt][nt][0] + lb0, acc[mt][nt][1] + lb1);
            if (gm1 < M)
                *(__half2*)(sup + (size_t)gm1 * D + n) =
                    __floats2half2_rn(acc[mt][nt][2] + lb0, acc[mt][nt][3] + lb1);
        }
    }
}

// ---------------------------------------------------------------------------
// Single-pass exclusive scan, decoupled lookback. state zeroed before launch.
// ---------------------------------------------------------------------------
__global__ void scan_kernel(int* __restrict__ rowptr, int* __restrict__ cursor,
                            unsigned long long* __restrict__ state, int N, int nE)
{
    __shared__ int s[1024];
    __shared__ int sprefix;
    const int b = blockIdx.x;
    const int i = b * 1024 + threadIdx.x;

    int v = (i < N) ? rowptr[i] : 0;
    s[threadIdx.x] = v;
    __syncthreads();
#pragma unroll
    for (int off = 1; off < 1024; off <<= 1) {
        int t = (threadIdx.x >= off) ? s[threadIdx.x - off] : 0;
        __syncthreads();
        s[threadIdx.x] += t;
        __syncthreads();
    }
    int total = s[1023];

    if (threadIdx.x == 0) {
        if (b == 0) {
            atomicExch(state + 0, (2ULL << 32) | (unsigned)total);
            sprefix = 0;
        } else {
            atomicExch(state + b, (1ULL << 32) | (unsigned)total);
            int sum = 0;
            int j = b - 1;
            while (true) {
                unsigned long long w;
                do { w = atomicOr(state + j, 0ULL); } while ((w >> 32) == 0ULL);
                sum += (int)(unsigned)w;
                if ((w >> 32) == 2ULL) break;
                j--;
            }
            atomicExch(state + b, (2ULL << 32) | (unsigned)(total + sum));
            sprefix = sum;
        }
    }
    __syncthreads();

    if (i < N) {
        int val = s[threadIdx.x] - v + sprefix;   // exclusive + block prefix
        rowptr[i] = val;
        cursor[i] = val;
    }
    if (i == 0) rowptr[N] = nE;
}

// ---------------------------------------------------------------------------
__global__ void scatter_kernel(const int* __restrict__ rows, const int* __restrict__ cols,
                               const float* __restrict__ vals, int* __restrict__ cursor,
                               uint2* __restrict__ edges, int nE)
{
    for (int e = blockIdx.x * blockDim.x + threadIdx.x; e < nE;
         e += gridDim.x * blockDim.x) {
        int r = __ldg(rows + e);
        int p = atomicAdd(cursor + r, 1);
        edges[p] = make_uint2((unsigned)__ldg(cols + e),
                              __float_as_uint(__ldg(vals + e)));
    }
}

// ---------------------------------------------------------------------------
// CSR SpMM: warp per row, 8-edge unroll (MLP=8).
// ---------------------------------------------------------------------------
__device__ __forceinline__ void fma_edge(float4& acc, uint2 q, float v)
{
    float2 a = __half22float2(*(__half2*)&q.x);
    float2 b = __half22float2(*(__half2*)&q.y);
    acc.x = fmaf(a.x, v, acc.x); acc.y = fmaf(a.y, v, acc.y);
    acc.z = fmaf(b.x, v, acc.z); acc.w = fmaf(b.y, v, acc.w);
}

__global__ void __launch_bounds__(256)
csr_kernel(const __half* __restrict__ sup, const uint2* __restrict__ edges,
           const int* __restrict__ rowptr, const float* __restrict__ bias,
           float* __restrict__ out, int N)
{
    int r = blockIdx.x * 8 + (threadIdx.x >> 5);
    if (r >= N) return;
    int lane = threadIdx.x & 31;

    int s = __ldg(rowptr + r);
    int e = __ldg(rowptr + r + 1);

    float4 acc = *(const float4*)(bias + lane * 4);

    int i = s;
    for (; i + 7 < e; i += 8) {
        uint2 ev[8], q[8];
#pragma unroll
        for (int j = 0; j < 8; j++) ev[j] = __ldg(edges + i + j);
#pragma unroll
        for (int j = 0; j < 8; j++)
            q[j] = *(const uint2*)(sup + (size_t)ev[j].x * D + lane * 4);
#pragma unroll
        for (int j = 0; j < 8; j++) fma_edge(acc, q[j], __uint_as_float(ev[j].y));
    }
    for (; i + 1 < e; i += 2) {
        uint2 ev0 = __ldg(edges + i);
        uint2 ev1 = __ldg(edges + i + 1);
        uint2 q0 = *(const uint2*)(sup + (size_t)ev0.x * D + lane * 4);
        uint2 q1 = *(const uint2*)(sup + (size_t)ev1.x * D + lane * 4);
        fma_edge(acc, q0, __uint_as_float(ev0.y));
        fma_edge(acc, q1, __uint_as_float(ev1.y));
    }
    if (i < e) {
        uint2 ev = __ldg(edges + i);
        uint2 q = *(const uint2*)(sup + (size_t)ev.x * D + lane * 4);
        fma_edge(acc, q, __uint_as_float(ev.y));
    }

    *(float4*)(out + (size_t)r * D + lane * 4) = acc;
}

// ---------------------------------------------------------------------------
extern "C" void kernel_launch(void* const* d_in, const int* in_sizes, int n_in,
                              void* d_out, int out_size)
{
    const float* x        = (const float*)d_in[0];
    const float* W        = (const float*)d_in[1];
    const float* lin_bias = (const float*)d_in[2];
    const float* bias     = (const float*)d_in[3];
    const int*   adj_rows = (const int*)d_in[4];
    const int*   adj_cols = (const int*)d_in[5];
    const float* adj_vals = (const float*)d_in[6];
    float* out = (float*)d_out;

    const int M  = in_sizes[0] / D;      // 100000
    const int nE = in_sizes[4];          // 1600000

    __half* sup = nullptr;   cudaGetSymbolAddress((void**)&sup, g_support);
    int* rowptr = nullptr;   cudaGetSymbolAddress((void**)&rowptr, g_rowptr);
    int* cursor = nullptr;   cudaGetSymbolAddress((void**)&cursor, g_cursor);
    unsigned long long* state = nullptr;
    cudaGetSymbolAddress((void**)&state, g_scanstate);
    uint2* edges = nullptr;  cudaGetSymbolAddress((void**)&edges, g_edges);

    const int NB = (M + 1023) / 1024;    // 98
    const int smem = (2 * 64 * WS32 + 2 * 2 * 128 * XS32) * sizeof(unsigned); // ~108.5 KB
    cudaFuncSetAttribute(gemm_hist_kernel, cudaFuncAttributeMaxDynamicSharedMemorySize, smem);

    cudaMemsetAsync(rowptr, 0, (M + 1) * sizeof(int));
    cudaMemsetAsync(state, 0, NB * sizeof(unsigned long long));

    const int gemmGrid = (M + 127) / 128;
    gemm_hist_kernel<<<HB + gemmGrid, 256, smem>>>(x, W, lin_bias, sup, M,
                                                   adj_rows, rowptr, nE);

    scan_kernel<<<NB, 1024>>>(rowptr, cursor, state, M, nE);
    scatter_kernel<<<256, 256>>>(adj_rows, adj_cols, adj_vals, cursor, edges, nE);
    csr_kernel<<<(M + 7) / 8, 256>>>(sup, edges, rowptr, bias, out, M);
}

// round 15
// speedup vs baseline: 1.0932x; 1.0932x over previous
#include <cuda_runtime.h>
#include <cuda_fp16.h>
#include <cuda_bf16.h>
#include <stdint.h>

// ---------------------------------------------------------------------------
// GraphConv: out = SpMM(adj, x@W + lin_bias) + bias
// gemm_hist: blocks [0,HB) do the edge histogram, rest do the bf16 3-term GEMM
//            (W staged once, single-buffer x with register prefetch, 86KB smem).
// Then: decoupled-lookback scan -> scatter (wide grid) -> warp-per-row csr.
// ---------------------------------------------------------------------------

#define D 128
#define TK 32
#define XS32 20
#define WS32 132
#define NMAX 100000
#define EMAX 1600000
#define HB 256

__device__ __half g_support[NMAX * D];
__device__ int    g_rowptr[NMAX + 1];
__device__ int    g_cursor[NMAX];
__device__ unsigned long long g_scanstate[128];
__device__ uint2  g_edges[EMAX];

// ---------------------------------------------------------------------------
__device__ __forceinline__ void split2_bf16(float a, float b, unsigned& hi, unsigned& lo)
{
    __nv_bfloat16 ah = __float2bfloat16_rn(a);
    __nv_bfloat16 bh = __float2bfloat16_rn(b);
    __nv_bfloat16 al = __float2bfloat16_rn(a - __bfloat162float(ah));
    __nv_bfloat16 bl = __float2bfloat16_rn(b - __bfloat162float(bh));
    __nv_bfloat162 H = __halves2bfloat162(ah, bh);
    __nv_bfloat162 L = __halves2bfloat162(al, bl);
    hi = *(unsigned*)&H;
    lo = *(unsigned*)&L;
}

__device__ __forceinline__ void mma_bf16(float* d, const unsigned* a, const unsigned* b)
{
    asm("mma.sync.aligned.m16n8k16.row.col.f32.bf16.bf16.f32 "
        "{%0,%1,%2,%3}, {%4,%5,%6,%7}, {%8,%9}, {%0,%1,%2,%3};"
        : "+f"(d[0]), "+f"(d[1]), "+f"(d[2]), "+f"(d[3])
        : "r"(a[0]), "r"(a[1]), "r"(a[2]), "r"(a[3]), "r"(b[0]), "r"(b[1]));
}

// ---------------------------------------------------------------------------
// Kernel 1: hist blocks + GEMM blocks in one launch (overlap on chip).
// GEMM identical to the proven R13 version (single xs buffer, reg prefetch).
// ---------------------------------------------------------------------------
__global__ void __launch_bounds__(256, 2)
gemm_hist_kernel(const float* __restrict__ x, const float* __restrict__ W,
                 const float* __restrict__ lin_bias, __half* __restrict__ sup, int M,
                 const int* __restrict__ rows, int* __restrict__ cnt, int nE)
{
    const int tid = threadIdx.x;

    if (blockIdx.x < HB) {
        for (int e = blockIdx.x * 256 + tid; e < nE; e += HB * 256)
            atomicAdd(cnt + __ldg(rows + e), 1);
        return;
    }

    extern __shared__ unsigned sh[];
    unsigned* ws_hi = sh;                        // [64][WS32]
    unsigned* ws_lo = ws_hi + 64 * WS32;
    unsigned* xs_hi = ws_lo + 64 * WS32;         // [128][XS32]
    unsigned* xs_lo = xs_hi + 128 * XS32;

    const int warp = tid >> 5;
    const int lane = tid & 31;
    const int g    = lane >> 2;
    const int t4   = lane & 3;

    const int rowBase = (blockIdx.x - HB) * 128;
    const int warpRow = (warp & 3) * 32;
    const int warpCol = (warp >> 2) * 64;

    // stage ALL of W once
    for (int i = tid; i < 64 * (D / 4); i += 256) {
        int k2 = i >> 5;
        int n4 = (i & 31) * 4;
        float4 va = *(const float4*)(W + (size_t)(2 * k2)     * D + n4);
        float4 vb = *(const float4*)(W + (size_t)(2 * k2 + 1) * D + n4);
        uint4 ph, pl;
        split2_bf16(va.x, vb.x, ph.x, pl.x);
        split2_bf16(va.y, vb.y, ph.y, pl.y);
        split2_bf16(va.z, vb.z, ph.z, pl.z);
        split2_bf16(va.w, vb.w, ph.w, pl.w);
        *(uint4*)(ws_hi + k2 * WS32 + n4) = ph;
        *(uint4*)(ws_lo + k2 * WS32 + n4) = pl;
    }

    float acc[2][8][4];
#pragma unroll
    for (int mt = 0; mt < 2; mt++)
#pragma unroll
        for (int nt = 0; nt < 8; nt++)
#pragma unroll
            for (int i = 0; i < 4; i++) acc[mt][nt][i] = 0.f;

    int sm[4], skq[4];
#pragma unroll
    for (int j = 0; j < 4; j++) {
        int i = tid + j * 256;
        sm[j]  = i >> 3;
        skq[j] = (i & 7) * 4;
    }

    float4 pre[4];
#pragma unroll
    for (int j = 0; j < 4; j++) {
        int gm = rowBase + sm[j];
        pre[j] = (gm < M) ? *(const float4*)(x + (size_t)gm * D + skq[j])
                          : make_float4(0.f, 0.f, 0.f, 0.f);
    }

#pragma unroll
    for (int c = 0; c < 4; c++) {
        if (c) __syncthreads();

#pragma unroll
        for (int j = 0; j < 4; j++) {
            unsigned h0, l0, h1, l1;
            split2_bf16(pre[j].x, pre[j].y, h0, l0);
            split2_bf16(pre[j].z, pre[j].w, h1, l1);
            *(uint2*)(xs_hi + sm[j] * XS32 + (skq[j] >> 1)) = make_uint2(h0, h1);
            *(uint2*)(xs_lo + sm[j] * XS32 + (skq[j] >> 1)) = make_uint2(l0, l1);
        }

        if (c < 3) {
            int k0n = (c + 1) * TK;
#pragma unroll
            for (int j = 0; j < 4; j++) {
                int gm = rowBase + sm[j];
                pre[j] = (gm < M) ? *(const float4*)(x + (size_t)gm * D + k0n + skq[j])
                                  : make_float4(0.f, 0.f, 0.f, 0.f);
            }
        }
        __syncthreads();

        const int kp0 = c * (TK / 2);
#pragma unroll
        for (int ks2 = 0; ks2 < TK / 2; ks2 += 8) {
            unsigned bh[8][2], bl[8][2];
#pragma unroll
            for (int nt = 0; nt < 8; nt++) {
                int col = warpCol + nt * 8 + g;
                int kr  = kp0 + ks2 + t4;
                bh[nt][0] = ws_hi[kr       * WS32 + col];
                bh[nt][1] = ws_hi[(kr + 4) * WS32 + col];
                bl[nt][0] = ws_lo[kr       * WS32 + col];
                bl[nt][1] = ws_lo[(kr + 4) * WS32 + col];
            }
#pragma unroll
            for (int mt = 0; mt < 2; mt++) {
                int r0 = warpRow + mt * 16 + g;
                unsigned ah[4], al[4];
                ah[0] = xs_hi[r0       * XS32 + ks2 + t4];
                ah[1] = xs_hi[(r0 + 8) * XS32 + ks2 + t4];
                ah[2] = xs_hi[r0       * XS32 + ks2 + t4 + 4];
                ah[3] = xs_hi[(r0 + 8) * XS32 + ks2 + t4 + 4];
                al[0] = xs_lo[r0       * XS32 + ks2 + t4];
                al[1] = xs_lo[(r0 + 8) * XS32 + ks2 + t4];
                al[2] = xs_lo[r0       * XS32 + ks2 + t4 + 4];
                al[3] = xs_lo[(r0 + 8) * XS32 + ks2 + t4 + 4];
#pragma unroll
                for (int nt = 0; nt < 8; nt++) {
                    mma_bf16(acc[mt][nt], ah, bh[nt]);
                    mma_bf16(acc[mt][nt], ah, bl[nt]);
                    mma_bf16(acc[mt][nt], al, bh[nt]);
                }
            }
        }
    }

#pragma unroll
    for (int nt = 0; nt < 8; nt++) {
        int n = warpCol + nt * 8 + t4 * 2;
        float lb0 = lin_bias[n];
        float lb1 = lin_bias[n + 1];
#pragma unroll
        for (int mt = 0; mt < 2; mt++) {
            int gm0 = rowBase + warpRow + mt * 16 + g;
            int gm1 = gm0 + 8;
            if (gm0 < M)
                *(__half2*)(sup + (size_t)gm0 * D + n) =
                    __floats2half2_rn(acc[mt][nt][0] + lb0, acc[mt][nt][1] + lb1);
            if (gm1 < M)
                *(__half2*)(sup + (size_t)gm1 * D + n) =
                    __floats2half2_rn(acc[mt][nt][2] + lb0, acc[mt][nt][3] + lb1);
        }
    }
}

// ---------------------------------------------------------------------------
// Single-pass exclusive scan, decoupled lookback (state zeroed per call).
// ---------------------------------------------------------------------------
__global__ void scan_kernel(int* __restrict__ rowptr, int* __restrict__ cursor,
                            unsigned long long* __restrict__ state, int N, int nE)
{
    __shared__ int s[1024];
    __shared__ int sprefix;
    const int b = blockIdx.x;
    const int i = b * 1024 + threadIdx.x;

    int v = (i < N) ? rowptr[i] : 0;
    s[threadIdx.x] = v;
    __syncthreads();
#pragma unroll
    for (int off = 1; off < 1024; off <<= 1) {
        int t = (threadIdx.x >= off) ? s[threadIdx.x - off] : 0;
        __syncthreads();
        s[threadIdx.x] += t;
        __syncthreads();
    }
    int total = s[1023];

    if (threadIdx.x == 0) {
        if (b == 0) {
            atomicExch(state + 0, (2ULL << 32) | (unsigned)total);
            sprefix = 0;
        } else {
            atomicExch(state + b, (1ULL << 32) | (unsigned)total);
            int sum = 0;
            int j = b - 1;
            while (true) {
                unsigned long long w;
                do { w = atomicOr(state + j, 0ULL); } while ((w >> 32) == 0ULL);
                sum += (int)(unsigned)w;
                if ((w >> 32) == 2ULL) break;
                j--;
            }
            atomicExch(state + b, (2ULL << 32) | (unsigned)(total + sum));
            sprefix = sum;
        }
    }
    __syncthreads();

    if (i < N) {
        int val = s[threadIdx.x] - v + sprefix;
        rowptr[i] = val;
        cursor[i] = val;
    }
    if (i == 0) rowptr[N] = nE;
}

// ---------------------------------------------------------------------------
__global__ void scatter_kernel(const int* __restrict__ rows, const int* __restrict__ cols,
                               const float* __restrict__ vals, int* __restrict__ cursor,
                               uint2* __restrict__ edges, int nE)
{
    for (int e = blockIdx.x * blockDim.x + threadIdx.x; e < nE;
         e += gridDim.x * blockDim.x) {
        int r = __ldg(rows + e);
        int p = atomicAdd(cursor + r, 1);
        edges[p] = make_uint2((unsigned)__ldg(cols + e),
                              __float_as_uint(__ldg(vals + e)));
    }
}

// ---------------------------------------------------------------------------
// CSR SpMM: warp per row, 4-edge unroll (proven best).
// ---------------------------------------------------------------------------
__device__ __forceinline__ void fma_edge(float4& acc, uint2 q, float v)
{
    float2 a = __half22float2(*(__half2*)&q.x);
    float2 b = __half22float2(*(__half2*)&q.y);
    acc.x = fmaf(a.x, v, acc.x); acc.y = fmaf(a.y, v, acc.y);
    acc.z = fmaf(b.x, v, acc.z); acc.w = fmaf(b.y, v, acc.w);
}

__global__ void __launch_bounds__(256)
csr_kernel(const __half* __restrict__ sup, const uint2* __restrict__ edges,
           const int* __restrict__ rowptr, const float* __restrict__ bias,
           float* __restrict__ out, int N)
{
    int r = blockIdx.x * 8 + (threadIdx.x >> 5);
    if (r >= N) return;
    int lane = threadIdx.x & 31;

    int s = __ldg(rowptr + r);
    int e = __ldg(rowptr + r + 1);

    float4 acc = *(const float4*)(bias + lane * 4);

    int i = s;
    for (; i + 3 < e; i += 4) {
        uint2 ev0 = __ldg(edges + i);
        uint2 ev1 = __ldg(edges + i + 1);
        uint2 ev2 = __ldg(edges + i + 2);
        uint2 ev3 = __ldg(edges + i + 3);
        uint2 q0 = *(const uint2*)(sup + (size_t)ev0.x * D + lane * 4);
        uint2 q1 = *(const uint2*)(sup + (size_t)ev1.x * D + lane * 4);
        uint2 q2 = *(const uint2*)(sup + (size_t)ev2.x * D + lane * 4);
        uint2 q3 = *(const uint2*)(sup + (size_t)ev3.x * D + lane * 4);
        fma_edge(acc, q0, __uint_as_float(ev0.y));
        fma_edge(acc, q1, __uint_as_float(ev1.y));
        fma_edge(acc, q2, __uint_as_float(ev2.y));
        fma_edge(acc, q3, __uint_as_float(ev3.y));
    }
    for (; i < e; i++) {
        uint2 ev = __ldg(edges + i);
        uint2 q = *(const uint2*)(sup + (size_t)ev.x * D + lane * 4);
        fma_edge(acc, q, __uint_as_float(ev.y));
    }

    *(float4*)(out + (size_t)r * D + lane * 4) = acc;
}

// ---------------------------------------------------------------------------
extern "C" void kernel_launch(void* const* d_in, const int* in_sizes, int n_in,
                              void* d_out, int out_size)
{
    const float* x        = (const float*)d_in[0];
    const float* W        = (const float*)d_in[1];
    const float* lin_bias = (const float*)d_in[2];
    const float* bias     = (const float*)d_in[3];
    const int*   adj_rows = (const int*)d_in[4];
    const int*   adj_cols = (const int*)d_in[5];
    const float* adj_vals = (const float*)d_in[6];
    float* out = (float*)d_out;

    const int M  = in_sizes[0] / D;      // 100000
    const int nE = in_sizes[4];          // 1600000

    __half* sup = nullptr;   cudaGetSymbolAddress((void**)&sup, g_support);
    int* rowptr = nullptr;   cudaGetSymbolAddress((void**)&rowptr, g_rowptr);
    int* cursor = nullptr;   cudaGetSymbolAddress((void**)&cursor, g_cursor);
    unsigned long long* state = nullptr;
    cudaGetSymbolAddress((void**)&state, g_scanstate);
    uint2* edges = nullptr;  cudaGetSymbolAddress((void**)&edges, g_edges);

    const int NB = (M + 1023) / 1024;    // 98
    const int smem = (2 * 64 * WS32 + 2 * 128 * XS32) * sizeof(unsigned); // ~86 KB
    cudaFuncSetAttribute(gemm_hist_kernel, cudaFuncAttributeMaxDynamicSharedMemorySize, smem);

    cudaMemsetAsync(rowptr, 0, (M + 1) * sizeof(int));
    cudaMemsetAsync(state, 0, NB * sizeof(unsigned long long));

    const int gemmGrid = (M + 127) / 128;
    gemm_hist_kernel<<<HB + gemmGrid, 256, smem>>>(x, W, lin_bias, sup, M,
                                                   adj_rows, rowptr, nE);

    scan_kernel<<<NB, 1024>>>(rowptr, cursor, state, M, nE);
    scatter_kernel<<<1024, 256>>>(adj_rows, adj_cols, adj_vals, cursor, edges, nE);
    csr_kernel<<<(M + 7) / 8, 256>>>(sup, edges, rowptr, bias, out, M);
}

// round 17
// speedup vs baseline: 1.1213x; 1.0257x over previous
#include <cuda_runtime.h>
#include <cuda_fp16.h>
#include <cuda_bf16.h>
#include <stdint.h>

// ---------------------------------------------------------------------------
// GraphConv: out = SpMM(adj, x@W + lin_bias) + bias
// ONE fused launch: [hist | gemm(bf16 3-term mma.sync) | scan(lookback) | scatter]
// with device-counter ordering, then warp-per-row csr gather.
// ---------------------------------------------------------------------------

#define D 128
#define TK 32
#define XS32 20
#define WS32 132
#define NMAX 100000
#define EMAX 1600000
#define HB 256          // hist blocks
#define SB 196          // scatter blocks (+98 scan <= 296 resident slots: deadlock-free)

struct CtrlBlock {
    int histDone;
    int scanDone;
    int pad[2];
    unsigned long long state[128];     // lookback: (flag<<32)|sum
    int rowptr[NMAX + 1];
};

__device__ CtrlBlock g_cb;
__device__ int    g_cursor[NMAX];
__device__ __half g_support[NMAX * D];
__device__ uint2  g_edges[EMAX];

// ---------------------------------------------------------------------------
__device__ __forceinline__ int ldcg(const int* p)
{
    int v;
    asm volatile("ld.global.cg.b32 %0, [%1];" : "=r"(v) : "l"(p));
    return v;
}

__device__ __forceinline__ void split2_bf16(float a, float b, unsigned& hi, unsigned& lo)
{
    __nv_bfloat16 ah = __float2bfloat16_rn(a);
    __nv_bfloat16 bh = __float2bfloat16_rn(b);
    __nv_bfloat16 al = __float2bfloat16_rn(a - __bfloat162float(ah));
    __nv_bfloat16 bl = __float2bfloat16_rn(b - __bfloat162float(bh));
    __nv_bfloat162 H = __halves2bfloat162(ah, bh);
    __nv_bfloat162 L = __halves2bfloat162(al, bl);
    hi = *(unsigned*)&H;
    lo = *(unsigned*)&L;
}

__device__ __forceinline__ void mma_bf16(float* d, const unsigned* a, const unsigned* b)
{
    asm("mma.sync.aligned.m16n8k16.row.col.f32.bf16.bf16.f32 "
        "{%0,%1,%2,%3}, {%4,%5,%6,%7}, {%8,%9}, {%0,%1,%2,%3};"
        : "+f"(d[0]), "+f"(d[1]), "+f"(d[2]), "+f"(d[3])
        : "r"(a[0]), "r"(a[1]), "r"(a[2]), "r"(a[3]), "r"(b[0]), "r"(b[1]));
}

// ---------------------------------------------------------------------------
// Fused kernel. Roles by blockIdx: [0,HB) hist, [HB,HB+GB) gemm,
// [HB+GB,HB+GB+NBLK) scan, rest scatter.
// ---------------------------------------------------------------------------
__global__ void __launch_bounds__(256, 2)
fused_kernel(const float* __restrict__ x, const float* __restrict__ W,
             const float* __restrict__ lin_bias, __half* __restrict__ sup, int M,
             const int* __restrict__ rows, const int* __restrict__ cols,
             const float* __restrict__ vals, int nE, int GB, int NBLK)
{
    const int tid = threadIdx.x;
    const int b = blockIdx.x;

    // ================= hist =================
    if (b < HB) {
        for (int e = b * 256 + tid; e < nE; e += HB * 256)
            atomicAdd(&g_cb.rowptr[__ldg(rows + e)], 1);
        __threadfence();
        __syncthreads();
        if (tid == 0) atomicAdd(&g_cb.histDone, 1);
        return;
    }

    // ================= gemm =================
    if (b < HB + GB) {
        extern __shared__ unsigned sh[];
        unsigned* ws_hi = sh;                        // [64][WS32]
        unsigned* ws_lo = ws_hi + 64 * WS32;
        unsigned* xs_hi = ws_lo + 64 * WS32;         // [128][XS32]
        unsigned* xs_lo = xs_hi + 128 * XS32;

        const int warp = tid >> 5;
        const int lane = tid & 31;
        const int g    = lane >> 2;
        const int t4   = lane & 3;

        const int rowBase = (b - HB) * 128;
        const int warpRow = (warp & 3) * 32;
        const int warpCol = (warp >> 2) * 64;

        for (int i = tid; i < 64 * (D / 4); i += 256) {
            int k2 = i >> 5;
            int n4 = (i & 31) * 4;
            float4 va = *(const float4*)(W + (size_t)(2 * k2)     * D + n4);
            float4 vb = *(const float4*)(W + (size_t)(2 * k2 + 1) * D + n4);
            uint4 ph, pl;
            split2_bf16(va.x, vb.x, ph.x, pl.x);
            split2_bf16(va.y, vb.y, ph.y, pl.y);
            split2_bf16(va.z, vb.z, ph.z, pl.z);
            split2_bf16(va.w, vb.w, ph.w, pl.w);
            *(uint4*)(ws_hi + k2 * WS32 + n4) = ph;
            *(uint4*)(ws_lo + k2 * WS32 + n4) = pl;
        }

        float acc[2][8][4];
#pragma unroll
        for (int mt = 0; mt < 2; mt++)
#pragma unroll
            for (int nt = 0; nt < 8; nt++)
#pragma unroll
                for (int i = 0; i < 4; i++) acc[mt][nt][i] = 0.f;

        int sm[4], skq[4];
#pragma unroll
        for (int j = 0; j < 4; j++) {
            int i = tid + j * 256;
            sm[j]  = i >> 3;
            skq[j] = (i & 7) * 4;
        }

        float4 pre[4];
#pragma unroll
        for (int j = 0; j < 4; j++) {
            int gm = rowBase + sm[j];
            pre[j] = (gm < M) ? *(const float4*)(x + (size_t)gm * D + skq[j])
                              : make_float4(0.f, 0.f, 0.f, 0.f);
        }

#pragma unroll
        for (int c = 0; c < 4; c++) {
            if (c) __syncthreads();

#pragma unroll
            for (int j = 0; j < 4; j++) {
                unsigned h0, l0, h1, l1;
                split2_bf16(pre[j].x, pre[j].y, h0, l0);
                split2_bf16(pre[j].z, pre[j].w, h1, l1);
                *(uint2*)(xs_hi + sm[j] * XS32 + (skq[j] >> 1)) = make_uint2(h0, h1);
                *(uint2*)(xs_lo + sm[j] * XS32 + (skq[j] >> 1)) = make_uint2(l0, l1);
            }

            if (c < 3) {
                int k0n = (c + 1) * TK;
#pragma unroll
                for (int j = 0; j < 4; j++) {
                    int gm = rowBase + sm[j];
                    pre[j] = (gm < M) ? *(const float4*)(x + (size_t)gm * D + k0n + skq[j])
                                      : make_float4(0.f, 0.f, 0.f, 0.f);
                }
            }
            __syncthreads();

            const int kp0 = c * (TK / 2);
#pragma unroll
            for (int ks2 = 0; ks2 < TK / 2; ks2 += 8) {
                unsigned bh[8][2], bl[8][2];
#pragma unroll
                for (int nt = 0; nt < 8; nt++) {
                    int col = warpCol + nt * 8 + g;
                    int kr  = kp0 + ks2 + t4;
                    bh[nt][0] = ws_hi[kr       * WS32 + col];
                    bh[nt][1] = ws_hi[(kr + 4) * WS32 + col];
                    bl[nt][0] = ws_lo[kr       * WS32 + col];
                    bl[nt][1] = ws_lo[(kr + 4) * WS32 + col];
                }
#pragma unroll
                for (int mt = 0; mt < 2; mt++) {
                    int r0 = warpRow + mt * 16 + g;
                    unsigned ah[4], al[4];
                    ah[0] = xs_hi[r0       * XS32 + ks2 + t4];
                    ah[1] = xs_hi[(r0 + 8) * XS32 + ks2 + t4];
                    ah[2] = xs_hi[r0       * XS32 + ks2 + t4 + 4];
                    ah[3] = xs_hi[(r0 + 8) * XS32 + ks2 + t4 + 4];
                    al[0] = xs_lo[r0       * XS32 + ks2 + t4];
                    al[1] = xs_lo[(r0 + 8) * XS32 + ks2 + t4];
                    al[2] = xs_lo[r0       * XS32 + ks2 + t4 + 4];
                    al[3] = xs_lo[(r0 + 8) * XS32 + ks2 + t4 + 4];
#pragma unroll
                    for (int nt = 0; nt < 8; nt++) {
                        mma_bf16(acc[mt][nt], ah, bh[nt]);
                        mma_bf16(acc[mt][nt], ah, bl[nt]);
                        mma_bf16(acc[mt][nt], al, bh[nt]);
                    }
                }
            }
        }

#pragma unroll
        for (int nt = 0; nt < 8; nt++) {
            int n = warpCol + nt * 8 + t4 * 2;
            float lb0 = lin_bias[n];
            float lb1 = lin_bias[n + 1];
#pragma unroll
            for (int mt = 0; mt < 2; mt++) {
                int gm0 = rowBase + warpRow + mt * 16 + g;
                int gm1 = gm0 + 8;
                if (gm0 < M)
                    *(__half2*)(sup + (size_t)gm0 * D + n) =
                        __floats2half2_rn(acc[mt][nt][0] + lb0, acc[mt][nt][1] + lb1);
                if (gm1 < M)
                    *(__half2*)(sup + (size_t)gm1 * D + n) =
                        __floats2half2_rn(acc[mt][nt][2] + lb0, acc[mt][nt][3] + lb1);
            }
        }
        return;
    }

    // ================= scan (decoupled lookback; 4 elems/thread) =================
    if (b < HB + GB + NBLK) {
        const int sb = b - HB - GB;
        __shared__ int ssum[8];
        __shared__ int spfx;
        const int lane = tid & 31;
        const int wp   = tid >> 5;

        if (tid == 0) {
            while (atomicAdd(&g_cb.histDone, 0) < HB) __nanosleep(100);
        }
        __syncthreads();
        __threadfence();

        const int base = sb * 1024 + tid * 4;
        int v0 = 0, v1 = 0, v2 = 0, v3 = 0;
        if (base + 0 < M) v0 = ldcg(&g_cb.rowptr[base + 0]);
        if (base + 1 < M) v1 = ldcg(&g_cb.rowptr[base + 1]);
        if (base + 2 < M) v2 = ldcg(&g_cb.rowptr[base + 2]);
        if (base + 3 < M) v3 = ldcg(&g_cb.rowptr[base + 3]);
        int tsum = v0 + v1 + v2 + v3;

        // warp inclusive scan of thread sums
        int incl = tsum;
#pragma unroll
        for (int off = 1; off < 32; off <<= 1) {
            int n = __shfl_up_sync(0xffffffffu, incl, off);
            if (lane >= off) incl += n;
        }
        if (lane == 31) ssum[wp] = incl;
        __syncthreads();
        if (tid < 32) {
            int xv = (tid < 8) ? ssum[tid] : 0;
#pragma unroll
            for (int off = 1; off < 8; off <<= 1) {
                int n = __shfl_up_sync(0xffffffffu, xv, off);
                if (tid >= off) xv += n;
            }
            if (tid < 8) ssum[tid] = xv;
        }
        __syncthreads();
        int woff = (wp == 0) ? 0 : ssum[wp - 1];
        int texcl = woff + incl - tsum;
        int btotal = ssum[7];

        if (tid == 0) {
            if (sb == 0) {
                atomicExch(&g_cb.state[0], (2ULL << 32) | (unsigned)btotal);
                spfx = 0;
            } else {
                atomicExch(&g_cb.state[sb], (1ULL << 32) | (unsigned)btotal);
                int sum = 0;
                int j = sb - 1;
                while (true) {
                    unsigned long long w;
                    do { w = atomicAdd(&g_cb.state[j], 0ULL); } while ((w >> 32) == 0ULL);
                    sum += (int)(unsigned)w;
                    if ((w >> 32) == 2ULL) break;
                    j--;
                }
                atomicExch(&g_cb.state[sb], (2ULL << 32) | (unsigned)(btotal + sum));
                spfx = sum;
            }
        }
        __syncthreads();

        int p = spfx + texcl;
        if (base + 0 < M) { g_cb.rowptr[base + 0] = p; g_cursor[base + 0] = p; } p += v0;
        if (base + 1 < M) { g_cb.rowptr[base + 1] = p; g_cursor[base + 1] = p; } p += v1;
        if (base + 2 < M) { g_cb.rowptr[base + 2] = p; g_cursor[base + 2] = p; } p += v2;
        if (base + 3 < M) { g_cb.rowptr[base + 3] = p; g_cursor[base + 3] = p; }
        if (sb == 0 && tid == 0) g_cb.rowptr[M] = nE;

        __threadfence();
        __syncthreads();
        if (tid == 0) atomicAdd(&g_cb.scanDone, 1);
        return;
    }

    // ================= scatter =================
    {
        const int cb = b - HB - GB - NBLK;
        if (tid == 0) {
            while (atomicAdd(&g_cb.scanDone, 0) < NBLK) __nanosleep(100);
        }
        __syncthreads();
        __threadfence();

        for (int e = cb * 256 + tid; e < nE; e += SB * 256) {
            int r = __ldg(rows + e);
            int p = atomicAdd(&g_cursor[r], 1);
            g_edges[p] = make_uint2((unsigned)__ldg(cols + e),
                                    __float_as_uint(__ldg(vals + e)));
        }
    }
}

// ---------------------------------------------------------------------------
// CSR SpMM: warp per row, 4-edge unroll.
// ---------------------------------------------------------------------------
__device__ __forceinline__ void fma_edge(float4& acc, uint2 q, float v)
{
    float2 a = __half22float2(*(__half2*)&q.x);
    float2 b = __half22float2(*(__half2*)&q.y);
    acc.x = fmaf(a.x, v, acc.x); acc.y = fmaf(a.y, v, acc.y);
    acc.z = fmaf(b.x, v, acc.z); acc.w = fmaf(b.y, v, acc.w);
}

__global__ void __launch_bounds__(256)
csr_kernel(const __half* __restrict__ sup, const float* __restrict__ bias,
           float* __restrict__ out, int N)
{
    int r = blockIdx.x * 8 + (threadIdx.x >> 5);
    if (r >= N) return;
    int lane = threadIdx.x & 31;

    int s = __ldg(&g_cb.rowptr[r]);
    int e = __ldg(&g_cb.rowptr[r + 1]);

    float4 acc = *(const float4*)(bias + lane * 4);

    int i = s;
    for (; i + 3 < e; i += 4) {
        uint2 ev0 = __ldg(&g_edges[i]);
        uint2 ev1 = __ldg(&g_edges[i + 1]);
        uint2 ev2 = __ldg(&g_edges[i + 2]);
        uint2 ev3 = __ldg(&g_edges[i + 3]);
        uint2 q0 = *(const uint2*)(sup + (size_t)ev0.x * D + lane * 4);
        uint2 q1 = *(const uint2*)(sup + (size_t)ev1.x * D + lane * 4);
        uint2 q2 = *(const uint2*)(sup + (size_t)ev2.x * D + lane * 4);
        uint2 q3 = *(const uint2*)(sup + (size_t)ev3.x * D + lane * 4);
        fma_edge(acc, q0, __uint_as_float(ev0.y));
        fma_edge(acc, q1, __uint_as_float(ev1.y));
        fma_edge(acc, q2, __uint_as_float(ev2.y));
        fma_edge(acc, q3, __uint_as_float(ev3.y));
    }
    for (; i < e; i++) {
        uint2 ev = __ldg(&g_edges[i]);
        uint2 q = *(const uint2*)(sup + (size_t)ev.x * D + lane * 4);
        fma_edge(acc, q, __uint_as_float(ev.y));
    }

    *(float4*)(out + (size_t)r * D + lane * 4) = acc;
}

// ---------------------------------------------------------------------------
extern "C" void kernel_launch(void* const* d_in, const int* in_sizes, int n_in,
                              void* d_out, int out_size)
{
    const float* x        = (const float*)d_in[0];
    const float* W        = (const float*)d_in[1];
    const float* lin_bias = (const float*)d_in[2];
    const float* bias     = (const float*)d_in[3];
    const int*   adj_rows = (const int*)d_in[4];
    const int*   adj_cols = (const int*)d_in[5];
    const float* adj_vals = (const float*)d_in[6];
    float* out = (float*)d_out;

    const int M  = in_sizes[0] / D;      // 100000
    const int nE = in_sizes[4];          // 1600000

    __half* sup = nullptr;   cudaGetSymbolAddress((void**)&sup, g_support);
    void* cbp = nullptr;     cudaGetSymbolAddress(&cbp, g_cb);

    const int GB   = (M + 127) / 128;    // 782
    const int NBLK = (M + 1023) / 1024;  // 98
    const int smem = (2 * 64 * WS32 + 2 * 128 * XS32) * sizeof(unsigned); // ~86 KB
    cudaFuncSetAttribute(fused_kernel, cudaFuncAttributeMaxDynamicSharedMemorySize, smem);

    // zero counters + lookback state + rowptr in ONE memset
    cudaMemsetAsync(cbp, 0, sizeof(CtrlBlock));

    fused_kernel<<<HB + GB + NBLK + SB, 256, smem>>>(
        x, W, lin_bias, sup, M, adj_rows, adj_cols, adj_vals, nE, GB, NBLK);

    csr_kernel<<<(M + 7) / 8, 256>>>(sup, bias, out, M);
}